// round 15
// baseline (speedup 1.0000x reference)
#include <cuda_runtime.h>
#include <cuda_bf16.h>
#include <math.h>

#define B 8
#define S 2048
#define D 2048
#define E 8
#define EPS 1e-5f

#define D4 (D / 4)            // 512 float4 per row
#define S_CHUNK 64            // rows per CTA (best-known)
#define GX 2                  // D4 / 256
#define GY (S / S_CHUNK)      // 32
#define NBLK (GX * GY * B)    // 512
#define LB 8                  // load batch depth (pinned by asm volatile)

// Scratch, zero-init; finalizing block re-zeroes for graph replay.
__device__ float g_acc[B * E + B];
__device__ float g_stats[2 * E];         // [mean, scale] per expert
__device__ unsigned int g_ticket;

// Pinned vector load: asm volatile prevents ptxas from sinking/interleaving,
// forcing all LB loads to issue back-to-back (true MLP depth = LB).
__device__ __forceinline__ float4 ldg4(const float4* p) {
    float4 v;
    asm volatile("ld.global.nc.v4.f32 {%0,%1,%2,%3}, [%4];"
                 : "=f"(v.x), "=f"(v.y), "=f"(v.z), "=f"(v.w)
                 : "l"(p));
    return v;
}

__global__ void __launch_bounds__(256) router_kernel(
    const float4* __restrict__ x4,
    const float4* __restrict__ W4,
    const float*  __restrict__ gain,
    const float*  __restrict__ init_std,
    const float*  __restrict__ noise,
    const int*    __restrict__ topk_p,
    float* __restrict__ out, int out_size)
{
    const int tid  = threadIdx.x;
    const int warp = tid >> 5, lane = tid & 31;
    const int d4   = blockIdx.x * 256 + tid;      // 0..511
    const int b    = blockIdx.z;
    const int s0   = blockIdx.y * S_CHUNK;
    const int bid  = (blockIdx.z * GY + blockIdx.y) * GX + blockIdx.x;

    // ---- stream x with pinned 8-deep load batches, 2 accumulators ----
    const float4* p = x4 + ((size_t)b * S + s0) * D4 + d4;
    float4 accA = make_float4(0.f, 0.f, 0.f, 0.f);
    float4 accB = make_float4(0.f, 0.f, 0.f, 0.f);
    for (int i = 0; i < S_CHUNK; i += LB) {
        float4 buf[LB];
#pragma unroll
        for (int j = 0; j < LB; j++)
            buf[j] = ldg4(&p[(size_t)(i + j) * D4]);   // 8 back-to-back LDGs
#pragma unroll
        for (int j = 0; j < LB; j += 2) {
            accA.x += buf[j].x;     accA.y += buf[j].y;
            accA.z += buf[j].z;     accA.w += buf[j].w;
            accB.x += buf[j + 1].x; accB.y += buf[j + 1].y;
            accB.z += buf[j + 1].z; accB.w += buf[j + 1].w;
        }
    }
    float4 acc = make_float4(accA.x + accB.x, accA.y + accB.y,
                             accA.z + accB.z, accA.w + accB.w);

    // ---- contract against W in-registers: 9 partials per thread ----
    float v9[9];
#pragma unroll
    for (int e = 0; e < E; e++) {
        float4 w = W4[e * D4 + d4];
        v9[e] = acc.x * w.x + acc.y * w.y + acc.z * w.z + acc.w * w.w;
    }
    v9[8] = acc.x + acc.y + acc.z + acc.w;        // xsum partial

    // ---- block reduce 9 values ----
    __shared__ float s_red[9][8];
#pragma unroll
    for (int o = 16; o; o >>= 1)
#pragma unroll
        for (int i = 0; i < 9; i++)
            v9[i] += __shfl_xor_sync(0xFFFFFFFFu, v9[i], o);
    if (lane == 0)
#pragma unroll
        for (int i = 0; i < 9; i++) s_red[i][warp] = v9[i];
    __syncthreads();
    if (tid < 9) {
        float s = 0.f;
#pragma unroll
        for (int w = 0; w < 8; w++) s += s_red[tid][w];
        atomicAdd(&g_acc[tid < 8 ? b * E + tid : 64 + b], s);
    }

    // ---- CTAs 0..7: per-expert W stats, overlapped with other CTAs' streams ----
    if (bid < E) {
        const int e = bid;
        const float4* wrow = W4 + e * D4;
        float s = 0.f, ss = 0.f;
#pragma unroll
        for (int i = 0; i < 2; i++) {
            float4 w = wrow[tid * 2 + i];          // 256 thr x 2 float4 = full row
            s  += w.x + w.y + w.z + w.w;
            ss += w.x * w.x + w.y * w.y + w.z * w.z + w.w * w.w;
        }
#pragma unroll
        for (int o = 16; o; o >>= 1) {
            s  += __shfl_xor_sync(0xFFFFFFFFu, s,  o);
            ss += __shfl_xor_sync(0xFFFFFFFFu, ss, o);
        }
        __shared__ float s_s[8], s_ss[8];
        if (lane == 0) { s_s[warp] = s; s_ss[warp] = ss; }
        __syncthreads();
        if (tid == 0) {
            float ts = 0.f, tss = 0.f;
#pragma unroll
            for (int w = 0; w < 8; w++) { ts += s_s[w]; tss += s_ss[w]; }
            float mean = ts / (float)D;
            float var  = (tss - (float)D * mean * mean) / (float)(D - 1);
            float std  = sqrtf(fmaxf(var, 0.f)) + EPS;
            g_stats[2 * e]     = mean;
            g_stats[2 * e + 1] = init_std[e] / std * gain[e];
        }
    }

    // ---- last-block ticket: one fence + one atomic per CTA ----
    __syncthreads();
    __shared__ bool is_last;
    if (tid == 0) {
        __threadfence();
        unsigned t = atomicAdd(&g_ticket, 1u);
        is_last = (t == NBLK - 1);
    }
    __syncthreads();
    if (!is_last) return;

    // ================= finalize (tiny, W stats already done) =================
    __shared__ float s_dot[B * E], s_xsum[B], s_scale[E], s_mean[E];
    if (tid < B * E) s_dot[tid]  = __ldcg(&g_acc[tid]);
    if (tid < B)     s_xsum[tid] = __ldcg(&g_acc[64 + tid]);
    if (tid < E) {
        s_mean[tid]  = __ldcg(&g_stats[2 * tid]);
        s_scale[tid] = __ldcg(&g_stats[2 * tid + 1]);
    }
    __syncthreads();

    if (tid < B) {
        const int bb = tid;
        int k = *topk_p;
        if (k > E) k = E;
        const float invS = 1.0f / (float)S;
        float sc[E];
        float mx = -INFINITY;
#pragma unroll
        for (int e = 0; e < E; e++) {
            float v = s_scale[e] * (s_dot[bb * E + e] - s_mean[e] * s_xsum[bb]) * invS
                      + noise[bb * E + e];
            sc[e] = v;
            mx = fmaxf(mx, v);
        }
        float denom = 0.f;
#pragma unroll
        for (int e = 0; e < E; e++) { sc[e] = expf(sc[e] - mx); denom += sc[e]; }
        float inv = 1.0f / denom;
#pragma unroll
        for (int e = 0; e < E; e++) sc[e] *= inv;

        float comb[E];
        bool taken[E];
#pragma unroll
        for (int e = 0; e < E; e++) { comb[e] = 0.f; taken[e] = false; }

        for (int kk = 0; kk < k; kk++) {
            int best = -1; float bv = -INFINITY;
            for (int e = 0; e < E; e++)
                if (!taken[e] && sc[e] > bv) { bv = sc[e]; best = e; }
            taken[best] = true;
            comb[best] = bv;
            int idx_off = B * E + bb * k + kk;
            int scr_off = B * E + B * k + bb * k + kk;
            if (idx_off < out_size) out[idx_off] = (float)best;
            if (scr_off < out_size) out[scr_off] = bv;
        }
#pragma unroll
        for (int e = 0; e < E; e++) {
            int o = bb * E + e;
            if (o < out_size) out[o] = comb[e];
        }
    }
    __syncthreads();

    // reset scratch for next graph replay
    if (tid < B * E + B) g_acc[tid] = 0.f;
    if (tid == 0) g_ticket = 0u;
}

extern "C" void kernel_launch(void* const* d_in, const int* in_sizes, int n_in,
                              void* d_out, int out_size) {
    const float* x        = (const float*)d_in[0];
    const float* W        = (const float*)d_in[1];
    const float* gain     = (const float*)d_in[2];
    const float* init_std = (const float*)d_in[3];
    const float* noise    = (const float*)d_in[4];
    const int*   topk     = (const int*)d_in[5];
    float* out = (float*)d_out;

    dim3 grid(GX, GY, B);
    router_kernel<<<grid, 256>>>((const float4*)x, (const float4*)W,
                                 gain, init_std, noise, topk, out, out_size);
}

// round 16
// speedup vs baseline: 1.0732x; 1.0732x over previous
#include <cuda_runtime.h>
#include <cuda_bf16.h>
#include <math.h>

#define B 8
#define S 2048
#define D 2048
#define E 8
#define EPS 1e-5f

#define D4 (D / 4)            // 512 float4 per row
#define S_CHUNK 64            // rows per CTA (best-known)
#define GX 2                  // D4 / 256
#define GY (S / S_CHUNK)      // 32
#define NBLK (GX * GY * B)    // 512
#define LB 16                 // load batch depth (pinned by asm volatile)

// Scratch, zero-init; finalizing block re-zeroes for graph replay.
__device__ float g_acc[B * E + B];
__device__ float g_stats[2 * E];         // [mean, scale] per expert
__device__ unsigned int g_ticket;

// Pinned vector load: asm volatile prevents ptxas from sinking/interleaving,
// forcing all LB loads to issue back-to-back (true MLP depth = LB).
__device__ __forceinline__ float4 ldg4(const float4* p) {
    float4 v;
    asm volatile("ld.global.nc.v4.f32 {%0,%1,%2,%3}, [%4];"
                 : "=f"(v.x), "=f"(v.y), "=f"(v.z), "=f"(v.w)
                 : "l"(p));
    return v;
}

__global__ void __launch_bounds__(256) router_kernel(
    const float4* __restrict__ x4,
    const float4* __restrict__ W4,
    const float*  __restrict__ gain,
    const float*  __restrict__ init_std,
    const float*  __restrict__ noise,
    const int*    __restrict__ topk_p,
    float* __restrict__ out, int out_size)
{
    const int tid  = threadIdx.x;
    const int warp = tid >> 5, lane = tid & 31;
    const int d4   = blockIdx.x * 256 + tid;      // 0..511
    const int b    = blockIdx.z;
    const int s0   = blockIdx.y * S_CHUNK;
    const int bid  = (blockIdx.z * GY + blockIdx.y) * GX + blockIdx.x;

    // ---- stream x with pinned 16-deep load batches, 4 accumulators ----
    const float4* p = x4 + ((size_t)b * S + s0) * D4 + d4;
    float4 accA = make_float4(0.f, 0.f, 0.f, 0.f);
    float4 accB = make_float4(0.f, 0.f, 0.f, 0.f);
    float4 accC = make_float4(0.f, 0.f, 0.f, 0.f);
    float4 accD = make_float4(0.f, 0.f, 0.f, 0.f);
    for (int i = 0; i < S_CHUNK; i += LB) {
        float4 buf[LB];
#pragma unroll
        for (int j = 0; j < LB; j++)
            buf[j] = ldg4(&p[(size_t)(i + j) * D4]);   // 16 back-to-back LDGs
#pragma unroll
        for (int j = 0; j < LB; j += 4) {
            accA.x += buf[j].x;     accA.y += buf[j].y;
            accA.z += buf[j].z;     accA.w += buf[j].w;
            accB.x += buf[j + 1].x; accB.y += buf[j + 1].y;
            accB.z += buf[j + 1].z; accB.w += buf[j + 1].w;
            accC.x += buf[j + 2].x; accC.y += buf[j + 2].y;
            accC.z += buf[j + 2].z; accC.w += buf[j + 2].w;
            accD.x += buf[j + 3].x; accD.y += buf[j + 3].y;
            accD.z += buf[j + 3].z; accD.w += buf[j + 3].w;
        }
    }
    float4 acc = make_float4(accA.x + accB.x + accC.x + accD.x,
                             accA.y + accB.y + accC.y + accD.y,
                             accA.z + accB.z + accC.z + accD.z,
                             accA.w + accB.w + accC.w + accD.w);

    // ---- contract against W in-registers: 9 partials per thread ----
    float v9[9];
#pragma unroll
    for (int e = 0; e < E; e++) {
        float4 w = W4[e * D4 + d4];
        v9[e] = acc.x * w.x + acc.y * w.y + acc.z * w.z + acc.w * w.w;
    }
    v9[8] = acc.x + acc.y + acc.z + acc.w;        // xsum partial

    // ---- block reduce 9 values ----
    __shared__ float s_red[9][8];
#pragma unroll
    for (int o = 16; o; o >>= 1)
#pragma unroll
        for (int i = 0; i < 9; i++)
            v9[i] += __shfl_xor_sync(0xFFFFFFFFu, v9[i], o);
    if (lane == 0)
#pragma unroll
        for (int i = 0; i < 9; i++) s_red[i][warp] = v9[i];
    __syncthreads();
    if (tid < 9) {
        float s = 0.f;
#pragma unroll
        for (int w = 0; w < 8; w++) s += s_red[tid][w];
        atomicAdd(&g_acc[tid < 8 ? b * E + tid : 64 + b], s);
    }

    // ---- CTAs 0..7: per-expert W stats, overlapped with other CTAs' streams ----
    if (bid < E) {
        const int e = bid;
        const float4* wrow = W4 + e * D4;
        float s = 0.f, ss = 0.f;
#pragma unroll
        for (int i = 0; i < 2; i++) {
            float4 w = wrow[tid * 2 + i];          // 256 thr x 2 float4 = full row
            s  += w.x + w.y + w.z + w.w;
            ss += w.x * w.x + w.y * w.y + w.z * w.z + w.w * w.w;
        }
#pragma unroll
        for (int o = 16; o; o >>= 1) {
            s  += __shfl_xor_sync(0xFFFFFFFFu, s,  o);
            ss += __shfl_xor_sync(0xFFFFFFFFu, ss, o);
        }
        __shared__ float s_s[8], s_ss[8];
        if (lane == 0) { s_s[warp] = s; s_ss[warp] = ss; }
        __syncthreads();
        if (tid == 0) {
            float ts = 0.f, tss = 0.f;
#pragma unroll
            for (int w = 0; w < 8; w++) { ts += s_s[w]; tss += s_ss[w]; }
            float mean = ts / (float)D;
            float var  = (tss - (float)D * mean * mean) / (float)(D - 1);
            float std  = sqrtf(fmaxf(var, 0.f)) + EPS;
            g_stats[2 * e]     = mean;
            g_stats[2 * e + 1] = init_std[e] / std * gain[e];
        }
    }

    // ---- last-block ticket: one fence + one atomic per CTA ----
    __syncthreads();
    __shared__ bool is_last;
    if (tid == 0) {
        __threadfence();
        unsigned t = atomicAdd(&g_ticket, 1u);
        is_last = (t == NBLK - 1);
    }
    __syncthreads();
    if (!is_last) return;

    // ================= finalize (tiny, W stats already done) =================
    __shared__ float s_dot[B * E], s_xsum[B], s_scale[E], s_mean[E];
    if (tid < B * E) s_dot[tid]  = __ldcg(&g_acc[tid]);
    if (tid < B)     s_xsum[tid] = __ldcg(&g_acc[64 + tid]);
    if (tid < E) {
        s_mean[tid]  = __ldcg(&g_stats[2 * tid]);
        s_scale[tid] = __ldcg(&g_stats[2 * tid + 1]);
    }
    __syncthreads();

    if (tid < B) {
        const int bb = tid;
        int k = *topk_p;
        if (k > E) k = E;
        const float invS = 1.0f / (float)S;
        float sc[E];
        float mx = -INFINITY;
#pragma unroll
        for (int e = 0; e < E; e++) {
            float v = s_scale[e] * (s_dot[bb * E + e] - s_mean[e] * s_xsum[bb]) * invS
                      + noise[bb * E + e];
            sc[e] = v;
            mx = fmaxf(mx, v);
        }
        float denom = 0.f;
#pragma unroll
        for (int e = 0; e < E; e++) { sc[e] = expf(sc[e] - mx); denom += sc[e]; }
        float inv = 1.0f / denom;
#pragma unroll
        for (int e = 0; e < E; e++) sc[e] *= inv;

        float comb[E];
        bool taken[E];
#pragma unroll
        for (int e = 0; e < E; e++) { comb[e] = 0.f; taken[e] = false; }

        for (int kk = 0; kk < k; kk++) {
            int best = -1; float bv = -INFINITY;
            for (int e = 0; e < E; e++)
                if (!taken[e] && sc[e] > bv) { bv = sc[e]; best = e; }
            taken[best] = true;
            comb[best] = bv;
            int idx_off = B * E + bb * k + kk;
            int scr_off = B * E + B * k + bb * k + kk;
            if (idx_off < out_size) out[idx_off] = (float)best;
            if (scr_off < out_size) out[scr_off] = bv;
        }
#pragma unroll
        for (int e = 0; e < E; e++) {
            int o = bb * E + e;
            if (o < out_size) out[o] = comb[e];
        }
    }
    __syncthreads();

    // reset scratch for next graph replay
    if (tid < B * E + B) g_acc[tid] = 0.f;
    if (tid == 0) g_ticket = 0u;
}

extern "C" void kernel_launch(void* const* d_in, const int* in_sizes, int n_in,
                              void* d_out, int out_size) {
    const float* x        = (const float*)d_in[0];
    const float* W        = (const float*)d_in[1];
    const float* gain     = (const float*)d_in[2];
    const float* init_std = (const float*)d_in[3];
    const float* noise    = (const float*)d_in[4];
    const int*   topk     = (const int*)d_in[5];
    float* out = (float*)d_out;

    dim3 grid(GX, GY, B);
    router_kernel<<<grid, 256>>>((const float4*)x, (const float4*)W,
                                 gain, init_std, noise, topk, out, out_size);
}